// round 1
// baseline (speedup 1.0000x reference)
#include <cuda_runtime.h>
#include <math.h>

#define HH 128
#define WW 256
#define CC 192
#define HWP (128*256)   // 32768 pixels per (b, channel)
#define NB 2

// ---------------- scratch (device globals; no allocs allowed) ----------------
__device__ float g_gate[NB * CC * HWP];          // 48 MB  silu(conv1x1(x, w_gate))
__device__ float g_t[NB * 3 * CC * HWP];         // 144 MB conv1x1(x, w_qkv)
__device__ float g_qkv[NB * 3 * CC * HWP];       // 144 MB depthwise(t)
__device__ float g_attn[NB * CC * HWP];          // 48 MB  attention output
__device__ float g_y[NB * CC * HWP];             // 48 MB  pre*gate

// ---------------- GEMM: Y[b,m,p] = sum_c W[m,c] * X[b,c,p] ------------------
// epi: 0 = none, 1 = silu, 2 = multiply by G[b,m,p]
#define BM 64
#define BN 128
#define BK 16

__global__ void __launch_bounds__(256) gemm_kernel(
    const float* __restrict__ W, const float* __restrict__ X,
    float* __restrict__ Y, const float* __restrict__ G, int M, int epi)
{
    __shared__ float As[BK][BM + 4];   // transposed, padded (bank + float4 align)
    __shared__ float Bs[BK][BN];

    const int b  = blockIdx.z;
    const int m0 = blockIdx.y * BM;
    const int n0 = blockIdx.x * BN;
    const float* Xb = X + (size_t)b * CC * HWP;

    const int tid   = threadIdx.x;
    const int a_row = tid >> 2;          // 0..63
    const int a_col = (tid & 3) << 2;    // 0,4,8,12
    const int b_row = tid >> 5;          // 0..7
    const int b_col = (tid & 31) << 2;   // 0..124
    const int tm    = (tid >> 5) << 3;   // warp -> 8 rows
    const int tn    = (tid & 31) << 2;   // lane -> 4 cols

    float acc[8][4];
#pragma unroll
    for (int i = 0; i < 8; i++)
#pragma unroll
        for (int j = 0; j < 4; j++) acc[i][j] = 0.f;

    for (int k0 = 0; k0 < CC; k0 += BK) {
        float4 av = *(const float4*)(W + (size_t)(m0 + a_row) * CC + k0 + a_col);
        As[a_col + 0][a_row] = av.x;
        As[a_col + 1][a_row] = av.y;
        As[a_col + 2][a_row] = av.z;
        As[a_col + 3][a_row] = av.w;
#pragma unroll
        for (int r = 0; r < 2; r++) {
            float4 bv = *(const float4*)(Xb + (size_t)(k0 + b_row + r * 8) * HWP + n0 + b_col);
            *(float4*)&Bs[b_row + r * 8][b_col] = bv;
        }
        __syncthreads();
#pragma unroll
        for (int k = 0; k < BK; k++) {
            float4 a0 = *(const float4*)&As[k][tm];
            float4 a1 = *(const float4*)&As[k][tm + 4];
            float4 bv = *(const float4*)&Bs[k][tn];
            float a[8] = {a0.x, a0.y, a0.z, a0.w, a1.x, a1.y, a1.z, a1.w};
            float bb[4] = {bv.x, bv.y, bv.z, bv.w};
#pragma unroll
            for (int i = 0; i < 8; i++)
#pragma unroll
                for (int j = 0; j < 4; j++)
                    acc[i][j] = fmaf(a[i], bb[j], acc[i][j]);
        }
        __syncthreads();
    }

    float* Yb = Y + (size_t)b * M * HWP;
    const float* Gb = (epi == 2) ? (G + (size_t)b * CC * HWP) : nullptr;
#pragma unroll
    for (int i = 0; i < 8; i++) {
        const int row = m0 + tm + i;
        float4 v = make_float4(acc[i][0], acc[i][1], acc[i][2], acc[i][3]);
        if (epi == 1) {
            v.x = v.x / (1.f + __expf(-v.x));
            v.y = v.y / (1.f + __expf(-v.y));
            v.z = v.z / (1.f + __expf(-v.z));
            v.w = v.w / (1.f + __expf(-v.w));
        } else if (epi == 2) {
            float4 g = *(const float4*)(Gb + (size_t)row * HWP + n0 + tn);
            v.x *= g.x; v.y *= g.y; v.z *= g.z; v.w *= g.w;
        }
        *(float4*)(Yb + (size_t)row * HWP + n0 + tn) = v;
    }
}

// ---------------- depthwise 3x3 (SAME padding, cross-correlation) -----------
__global__ void __launch_bounds__(256) dw_kernel(
    const float* __restrict__ t, const float* __restrict__ wd, float* __restrict__ out)
{
    const int y  = blockIdx.x;        // 0..127
    const int cb = blockIdx.y;        // 0..NB*576-1
    const int c  = cb % (3 * CC);
    const int x  = threadIdx.x;       // 0..255
    const float* base = t + (size_t)cb * HWP;

    float w[9];
#pragma unroll
    for (int i = 0; i < 9; i++) w[i] = wd[c * 9 + i];

    float acc = 0.f;
#pragma unroll
    for (int dy = -1; dy <= 1; dy++) {
        const int yy = y + dy;
        if (yy < 0 || yy >= HH) continue;
#pragma unroll
        for (int dx = -1; dx <= 1; dx++) {
            const int xx = x + dx;
            if (xx < 0 || xx >= WW) continue;
            acc = fmaf(base[yy * WW + xx], w[(dy + 1) * 3 + (dx + 1)], acc);
        }
    }
    out[(size_t)cb * HWP + y * WW + x] = acc;
}

// ---------------- row attention ---------------------------------------------
// One block per (b, row, head). 256 threads = 256 queries. K/V streamed in
// 64-wide j-chunks through smem; online softmax; relpos bias column in smem.
#define JC 64

__global__ void __launch_bounds__(256) attn_kernel(
    const float* __restrict__ qkv, const float* __restrict__ rpb, float* __restrict__ out)
{
    __shared__ float Kc[JC][36];
    __shared__ float Vc[JC][36];
    __shared__ float bsh[512];

    const int row = blockIdx.x, head = blockIdx.y, b = blockIdx.z;
    const int tid = threadIdx.x;                 // query index i
    const size_t base = (((size_t)b * (3 * CC) + head * 32) * HH + row) * WW;
    const size_t koff = (size_t)CC * HWP;        // +192 channels
    const size_t voff = 2 * koff;

    for (int i = tid; i < 511; i += 256) bsh[i] = rpb[i * 6 + head];

    float q[32];
#pragma unroll
    for (int d = 0; d < 32; d++) q[d] = qkv[base + (size_t)d * HWP + tid];

    const float scale = 0.17677669529663687f;    // 32^-0.5
    float m = -1e30f, l = 0.f;
    float o[32];
#pragma unroll
    for (int d = 0; d < 32; d++) o[d] = 0.f;

    for (int jt = 0; jt < WW; jt += JC) {
        __syncthreads();   // previous chunk fully consumed
        // load K/V chunk: 64 rows x 32 dims each; coalesced along j
        for (int i = tid; i < JC * 32; i += 256) {
            const int j = i & (JC - 1);
            const int d = i >> 6;               // 0..3 per pass, 8 passes via stride
            // i in [0, 2048): d = i/64 covers 0..31
            Kc[j][i >> 6] = qkv[base + koff + (size_t)d * HWP + jt + j];
            Vc[j][i >> 6] = qkv[base + voff + (size_t)d * HWP + jt + j];
        }
        __syncthreads();

        float s[JC];
#pragma unroll
        for (int jj = 0; jj < JC; jj++) {
            const float4* kp = (const float4*)&Kc[jj][0];
            float acc = 0.f;
#pragma unroll
            for (int c4 = 0; c4 < 8; c4++) {
                float4 kv = kp[c4];
                acc = fmaf(q[c4 * 4 + 0], kv.x, acc);
                acc = fmaf(q[c4 * 4 + 1], kv.y, acc);
                acc = fmaf(q[c4 * 4 + 2], kv.z, acc);
                acc = fmaf(q[c4 * 4 + 3], kv.w, acc);
            }
            s[jj] = acc * scale + bsh[tid - (jt + jj) + 255];
        }
        float mc = m;
#pragma unroll
        for (int jj = 0; jj < JC; jj++) mc = fmaxf(mc, s[jj]);
        const float corr = __expf(m - mc);
        l *= corr;
#pragma unroll
        for (int d = 0; d < 32; d++) o[d] *= corr;
#pragma unroll
        for (int jj = 0; jj < JC; jj++) {
            const float p = __expf(s[jj] - mc);
            l += p;
            const float4* vp = (const float4*)&Vc[jj][0];
#pragma unroll
            for (int c4 = 0; c4 < 8; c4++) {
                float4 vv = vp[c4];
                o[c4 * 4 + 0] = fmaf(p, vv.x, o[c4 * 4 + 0]);
                o[c4 * 4 + 1] = fmaf(p, vv.y, o[c4 * 4 + 1]);
                o[c4 * 4 + 2] = fmaf(p, vv.z, o[c4 * 4 + 2]);
                o[c4 * 4 + 3] = fmaf(p, vv.w, o[c4 * 4 + 3]);
            }
        }
        m = mc;
    }

    const float inv = 1.f / l;
    const size_t obase = (((size_t)b * CC + head * 32) * HH + row) * WW;
#pragma unroll
    for (int d = 0; d < 32; d++)
        out[obase + (size_t)d * HWP + tid] = o[d] * inv;
}

// ---------------- launch ------------------------------------------------------
extern "C" void kernel_launch(void* const* d_in, const int* in_sizes, int n_in,
                              void* d_out, int out_size)
{
    const float* x       = (const float*)d_in[0];
    const float* rpb     = (const float*)d_in[1];
    const float* w_qkv   = (const float*)d_in[2];
    const float* w_depth = (const float*)d_in[3];
    const float* w_pre   = (const float*)d_in[4];
    const float* w_out   = (const float*)d_in[5];
    const float* w_gate  = (const float*)d_in[6];
    float* out = (float*)d_out;
    (void)in_sizes; (void)n_in; (void)out_size;

    float *gate, *t, *qkv, *attn, *y;
    cudaGetSymbolAddress((void**)&gate, g_gate);
    cudaGetSymbolAddress((void**)&t,    g_t);
    cudaGetSymbolAddress((void**)&qkv,  g_qkv);
    cudaGetSymbolAddress((void**)&attn, g_attn);
    cudaGetSymbolAddress((void**)&y,    g_y);

    const dim3 gSmall(HWP / BN, CC / BM, NB);        // (256, 3, 2)
    const dim3 gQkv(HWP / BN, 3 * CC / BM, NB);      // (256, 9, 2)

    // 1) gate = silu(W_gate @ x)
    gemm_kernel<<<gSmall, 256>>>(w_gate, x, gate, nullptr, CC, 1);
    // 2) t = W_qkv @ x
    gemm_kernel<<<gQkv, 256>>>(w_qkv, x, t, nullptr, 3 * CC, 0);
    // 3) qkv = depthwise3x3(t)
    dw_kernel<<<dim3(HH, NB * 3 * CC), 256>>>(t, w_depth, qkv);
    // 4) attention per (b, row, head)
    attn_kernel<<<dim3(HH, 6, NB), 256>>>(qkv, rpb, attn);
    // 5) y = (W_pre @ attn) * gate
    gemm_kernel<<<gSmall, 256>>>(w_pre, attn, y, gate, CC, 2);
    // 6) out = W_out @ y
    gemm_kernel<<<gSmall, 256>>>(w_out, y, out, nullptr, CC, 0);
}

// round 2
// speedup vs baseline: 1.1506x; 1.1506x over previous
#include <cuda_runtime.h>
#include <cuda_bf16.h>
#include <math.h>
#include <stdint.h>

#define HH 128
#define WW 256
#define CC 192
#define HWP (128*256)
#define NB 2

// ---------------- scratch (device globals; no allocs allowed) ----------------
__device__ float g_gate[NB * CC * HWP];             // silu(conv1x1(x, w_gate))
__device__ float g_t[NB * 3 * CC * HWP];            // conv1x1(x, w_qkv)
__device__ float g_qkv[NB * 3 * CC * HWP];          // depthwise(t)
__device__ __nv_bfloat16 g_xhi[NB * CC * HWP];      // split of x
__device__ __nv_bfloat16 g_xlo[NB * CC * HWP];
__device__ __nv_bfloat16 g_ahi[NB * CC * HWP];      // split of attention output
__device__ __nv_bfloat16 g_alo[NB * CC * HWP];
__device__ __nv_bfloat16 g_yhi[NB * CC * HWP];      // split of pre*gate
__device__ __nv_bfloat16 g_ylo[NB * CC * HWP];

// ---------------- fp32 -> (hi,lo) bf16 split --------------------------------
__global__ void __launch_bounds__(256) split_kernel(
    const float* __restrict__ x, __nv_bfloat16* __restrict__ hi,
    __nv_bfloat16* __restrict__ lo, int n)
{
    int i = blockIdx.x * 256 + threadIdx.x;
    if (i < n) {
        float v = x[i];
        __nv_bfloat16 h = __float2bfloat16(v);
        hi[i] = h;
        lo[i] = __float2bfloat16(v - __bfloat162float(h));
    }
}

// ---------------- bf16 mma helper -------------------------------------------
__device__ __forceinline__ void mma16816(float* c, const uint32_t* a,
                                         uint32_t b0, uint32_t b1)
{
    asm volatile(
        "mma.sync.aligned.m16n8k16.row.col.f32.bf16.bf16.f32 "
        "{%0,%1,%2,%3}, {%4,%5,%6,%7}, {%8,%9}, {%0,%1,%2,%3};\n"
        : "+f"(c[0]), "+f"(c[1]), "+f"(c[2]), "+f"(c[3])
        : "r"(a[0]), "r"(a[1]), "r"(a[2]), "r"(a[3]), "r"(b0), "r"(b1));
}

// ---------------- split-bf16 tensor-core GEMM --------------------------------
// Y[b,m,p] = sum_c W[m,c] * X[b,c,p], with X given as bf16 hi/lo split.
// Y ~= Wh*Xh + Wh*Xl + Wl*Xh  (fp32 accumulate)
// Block: 256 thr (8 warps, 2x4), tile 64(m) x 256(n), BK=16.
// epi: 0 = f32 out; 1 = silu -> f32 out; 2 = (*G) -> bf16 hi/lo out.
__global__ void __launch_bounds__(256, 2) gemm_bf16_kernel(
    const float* __restrict__ W,
    const __nv_bfloat16* __restrict__ Xhi, const __nv_bfloat16* __restrict__ Xlo,
    float* __restrict__ Yf, const float* __restrict__ G,
    __nv_bfloat16* __restrict__ Yhi, __nv_bfloat16* __restrict__ Ylo,
    int M, int epi)
{
    __shared__ __nv_bfloat16 As[2][64][18];    // [half][m][k], row stride 18
    __shared__ __nv_bfloat16 Bs[2][256][18];   // [half][n][k]

    const int b  = blockIdx.z;
    const int m0 = blockIdx.y * 64;
    const int n0 = blockIdx.x * 256;
    const size_t xoff = (size_t)b * CC * HWP;

    const int tid  = threadIdx.x;
    const int lane = tid & 31;
    const int warp = tid >> 5;
    const int wm   = (warp >> 2) * 32;     // warp m-offset (0/32)
    const int wn   = (warp & 3) * 64;      // warp n-offset (0..192)
    const int gq   = lane >> 2;            // quad group 0..7
    const int tg   = lane & 3;             // thread-in-group

    const int ar  = tid >> 2;              // A-load row 0..63
    const int ac4 = (tid & 3) * 4;         // A-load col 0,4,8,12
    const int bn2 = 2 * lane;              // B-load n pair base

    float acc[2][8][4];
#pragma unroll
    for (int mt = 0; mt < 2; mt++)
#pragma unroll
        for (int nt = 0; nt < 8; nt++)
#pragma unroll
            for (int i = 0; i < 4; i++) acc[mt][nt][i] = 0.f;

    for (int k0 = 0; k0 < CC; k0 += 16) {
        // stage global loads in regs
        float4 av = *(const float4*)(W + (size_t)(m0 + ar) * CC + k0 + ac4);
        uint32_t bh[2][4], bl[2][4];
#pragma unroll
        for (int r = 0; r < 2; r++) {
            const int k = warp + 8 * r;
#pragma unroll
            for (int j = 0; j < 4; j++) {
                const size_t off = xoff + (size_t)(k0 + k) * HWP + n0 + bn2 + 64 * j;
                bh[r][j] = *(const uint32_t*)(Xhi + off);
                bl[r][j] = *(const uint32_t*)(Xlo + off);
            }
        }
        __syncthreads();   // previous tile consumed
        // A: convert fp32 -> hi/lo
        {
            float vs[4] = {av.x, av.y, av.z, av.w};
#pragma unroll
            for (int i = 0; i < 4; i++) {
                __nv_bfloat16 h = __float2bfloat16(vs[i]);
                As[0][ar][ac4 + i] = h;
                As[1][ar][ac4 + i] = __float2bfloat16(vs[i] - __bfloat162float(h));
            }
        }
        // B: transpose [k][n] -> [n][k]
#pragma unroll
        for (int r = 0; r < 2; r++) {
            const int k = warp + 8 * r;
#pragma unroll
            for (int j = 0; j < 4; j++) {
                const int n = bn2 + 64 * j;
                __nv_bfloat162 hv = *reinterpret_cast<__nv_bfloat162*>(&bh[r][j]);
                __nv_bfloat162 lv = *reinterpret_cast<__nv_bfloat162*>(&bl[r][j]);
                Bs[0][n][k] = hv.x; Bs[0][n + 1][k] = hv.y;
                Bs[1][n][k] = lv.x; Bs[1][n + 1][k] = lv.y;
            }
        }
        __syncthreads();

        // A fragments (both halves, both m-tiles)
        uint32_t af[2][2][4];
#pragma unroll
        for (int h = 0; h < 2; h++)
#pragma unroll
            for (int mt = 0; mt < 2; mt++) {
                const int rb = wm + mt * 16;
                af[h][mt][0] = *(const uint32_t*)&As[h][rb + gq][2 * tg];
                af[h][mt][1] = *(const uint32_t*)&As[h][rb + 8 + gq][2 * tg];
                af[h][mt][2] = *(const uint32_t*)&As[h][rb + gq][8 + 2 * tg];
                af[h][mt][3] = *(const uint32_t*)&As[h][rb + 8 + gq][8 + 2 * tg];
            }
#pragma unroll
        for (int nt = 0; nt < 8; nt++) {
            const int nr = wn + nt * 8 + gq;
            uint32_t bh0 = *(const uint32_t*)&Bs[0][nr][2 * tg];
            uint32_t bh1 = *(const uint32_t*)&Bs[0][nr][8 + 2 * tg];
            uint32_t bl0 = *(const uint32_t*)&Bs[1][nr][2 * tg];
            uint32_t bl1 = *(const uint32_t*)&Bs[1][nr][8 + 2 * tg];
#pragma unroll
            for (int mt = 0; mt < 2; mt++) {
                mma16816(acc[mt][nt], af[0][mt], bh0, bh1);  // hi*hi
                mma16816(acc[mt][nt], af[0][mt], bl0, bl1);  // hi*lo
                mma16816(acc[mt][nt], af[1][mt], bh0, bh1);  // lo*hi
            }
        }
    }

    // epilogue
    const size_t yoff = (size_t)b * M * HWP;
    const size_t goff = (size_t)b * CC * HWP;
#pragma unroll
    for (int mt = 0; mt < 2; mt++) {
        const int r0 = m0 + wm + mt * 16 + gq;
        const int r1 = r0 + 8;
#pragma unroll
        for (int nt = 0; nt < 8; nt++) {
            const int c = n0 + wn + nt * 8 + 2 * tg;
            float v00 = acc[mt][nt][0], v01 = acc[mt][nt][1];
            float v10 = acc[mt][nt][2], v11 = acc[mt][nt][3];
            if (epi == 1) {
                v00 = v00 / (1.f + __expf(-v00));
                v01 = v01 / (1.f + __expf(-v01));
                v10 = v10 / (1.f + __expf(-v10));
                v11 = v11 / (1.f + __expf(-v11));
            }
            if (epi == 2) {
                float2 g0 = *(const float2*)(G + goff + (size_t)r0 * HWP + c);
                float2 g1 = *(const float2*)(G + goff + (size_t)r1 * HWP + c);
                v00 *= g0.x; v01 *= g0.y; v10 *= g1.x; v11 *= g1.y;
                __nv_bfloat16 h00 = __float2bfloat16(v00);
                __nv_bfloat16 h01 = __float2bfloat16(v01);
                __nv_bfloat16 h10 = __float2bfloat16(v10);
                __nv_bfloat16 h11 = __float2bfloat16(v11);
                __nv_bfloat162 hh0; hh0.x = h00; hh0.y = h01;
                __nv_bfloat162 hh1; hh1.x = h10; hh1.y = h11;
                __nv_bfloat162 ll0; ll0.x = __float2bfloat16(v00 - __bfloat162float(h00));
                ll0.y = __float2bfloat16(v01 - __bfloat162float(h01));
                __nv_bfloat162 ll1; ll1.x = __float2bfloat16(v10 - __bfloat162float(h10));
                ll1.y = __float2bfloat16(v11 - __bfloat162float(h11));
                *(__nv_bfloat162*)(Yhi + yoff + (size_t)r0 * HWP + c) = hh0;
                *(__nv_bfloat162*)(Yhi + yoff + (size_t)r1 * HWP + c) = hh1;
                *(__nv_bfloat162*)(Ylo + yoff + (size_t)r0 * HWP + c) = ll0;
                *(__nv_bfloat162*)(Ylo + yoff + (size_t)r1 * HWP + c) = ll1;
            } else {
                *(float2*)(Yf + yoff + (size_t)r0 * HWP + c) = make_float2(v00, v01);
                *(float2*)(Yf + yoff + (size_t)r1 * HWP + c) = make_float2(v10, v11);
            }
        }
    }
}

// ---------------- depthwise 3x3 (SAME padding) ------------------------------
__global__ void __launch_bounds__(256) dw_kernel(
    const float* __restrict__ t, const float* __restrict__ wd, float* __restrict__ out)
{
    const int y  = blockIdx.x;
    const int cb = blockIdx.y;
    const int c  = cb % (3 * CC);
    const int x  = threadIdx.x;
    const float* base = t + (size_t)cb * HWP;

    float w[9];
#pragma unroll
    for (int i = 0; i < 9; i++) w[i] = wd[c * 9 + i];

    float acc = 0.f;
#pragma unroll
    for (int dy = -1; dy <= 1; dy++) {
        const int yy = y + dy;
        if (yy < 0 || yy >= HH) continue;
#pragma unroll
        for (int dx = -1; dx <= 1; dx++) {
            const int xx = x + dx;
            if (xx < 0 || xx >= WW) continue;
            acc = fmaf(base[yy * WW + xx], w[(dy + 1) * 3 + (dx + 1)], acc);
        }
    }
    out[(size_t)cb * HWP + y * WW + x] = acc;
}

// ---------------- row attention (JC=16: no spills) --------------------------
#define JC 16

__global__ void __launch_bounds__(256, 2) attn_kernel(
    const float* __restrict__ qkv, const float* __restrict__ rpb,
    __nv_bfloat16* __restrict__ ohi, __nv_bfloat16* __restrict__ olo)
{
    __shared__ float Kc[JC][36];
    __shared__ float Vc[JC][36];
    __shared__ float bsh[512];

    const int row = blockIdx.x, head = blockIdx.y, b = blockIdx.z;
    const int tid = threadIdx.x;                 // query index i
    const size_t base = (((size_t)b * (3 * CC) + head * 32) * HH + row) * WW;
    const size_t koff = (size_t)CC * HWP;
    const size_t voff = 2 * koff;

    for (int i = tid; i < 511; i += 256) bsh[i] = rpb[i * 6 + head];

    float q[32];
#pragma unroll
    for (int d = 0; d < 32; d++) q[d] = qkv[base + (size_t)d * HWP + tid];

    const float scale = 0.17677669529663687f;
    float m = -1e30f, l = 0.f;
    float o[32];
#pragma unroll
    for (int d = 0; d < 32; d++) o[d] = 0.f;

    for (int jt = 0; jt < WW; jt += JC) {
        __syncthreads();
        for (int i = tid; i < JC * 32; i += 256) {
            const int j = i & (JC - 1);
            const int d = i >> 4;
            Kc[j][d] = qkv[base + koff + (size_t)d * HWP + jt + j];
            Vc[j][d] = qkv[base + voff + (size_t)d * HWP + jt + j];
        }
        __syncthreads();

        float s[JC];
#pragma unroll
        for (int jj = 0; jj < JC; jj++) {
            const float4* kp = (const float4*)&Kc[jj][0];
            float acc = 0.f;
#pragma unroll
            for (int c4 = 0; c4 < 8; c4++) {
                float4 kv = kp[c4];
                acc = fmaf(q[c4 * 4 + 0], kv.x, acc);
                acc = fmaf(q[c4 * 4 + 1], kv.y, acc);
                acc = fmaf(q[c4 * 4 + 2], kv.z, acc);
                acc = fmaf(q[c4 * 4 + 3], kv.w, acc);
            }
            s[jj] = acc * scale + bsh[tid - (jt + jj) + 255];
        }
        float mc = m;
#pragma unroll
        for (int jj = 0; jj < JC; jj++) mc = fmaxf(mc, s[jj]);
        const float corr = __expf(m - mc);
        l *= corr;
#pragma unroll
        for (int d = 0; d < 32; d++) o[d] *= corr;
#pragma unroll
        for (int jj = 0; jj < JC; jj++) {
            const float p = __expf(s[jj] - mc);
            l += p;
            const float4* vp = (const float4*)&Vc[jj][0];
#pragma unroll
            for (int c4 = 0; c4 < 8; c4++) {
                float4 vv = vp[c4];
                o[c4 * 4 + 0] = fmaf(p, vv.x, o[c4 * 4 + 0]);
                o[c4 * 4 + 1] = fmaf(p, vv.y, o[c4 * 4 + 1]);
                o[c4 * 4 + 2] = fmaf(p, vv.z, o[c4 * 4 + 2]);
                o[c4 * 4 + 3] = fmaf(p, vv.w, o[c4 * 4 + 3]);
            }
        }
        m = mc;
    }

    const float inv = 1.f / l;
    const size_t obase = (((size_t)b * CC + head * 32) * HH + row) * WW;
#pragma unroll
    for (int d = 0; d < 32; d++) {
        const float v = o[d] * inv;
        __nv_bfloat16 h = __float2bfloat16(v);
        ohi[obase + (size_t)d * HWP + tid] = h;
        olo[obase + (size_t)d * HWP + tid] = __float2bfloat16(v - __bfloat162float(h));
    }
}

// ---------------- launch ------------------------------------------------------
extern "C" void kernel_launch(void* const* d_in, const int* in_sizes, int n_in,
                              void* d_out, int out_size)
{
    const float* x       = (const float*)d_in[0];
    const float* rpb     = (const float*)d_in[1];
    const float* w_qkv   = (const float*)d_in[2];
    const float* w_depth = (const float*)d_in[3];
    const float* w_pre   = (const float*)d_in[4];
    const float* w_out   = (const float*)d_in[5];
    const float* w_gate  = (const float*)d_in[6];
    float* out = (float*)d_out;
    (void)in_sizes; (void)n_in; (void)out_size;

    float *gate, *t, *qkv;
    __nv_bfloat16 *xhi, *xlo, *ahi, *alo, *yhi, *ylo;
    cudaGetSymbolAddress((void**)&gate, g_gate);
    cudaGetSymbolAddress((void**)&t,    g_t);
    cudaGetSymbolAddress((void**)&qkv,  g_qkv);
    cudaGetSymbolAddress((void**)&xhi,  g_xhi);
    cudaGetSymbolAddress((void**)&xlo,  g_xlo);
    cudaGetSymbolAddress((void**)&ahi,  g_ahi);
    cudaGetSymbolAddress((void**)&alo,  g_alo);
    cudaGetSymbolAddress((void**)&yhi,  g_yhi);
    cudaGetSymbolAddress((void**)&ylo,  g_ylo);

    const int nx = NB * CC * HWP;
    split_kernel<<<(nx + 255) / 256, 256>>>(x, xhi, xlo, nx);

    const dim3 gSmall(HWP / 256, CC / 64, NB);        // (128, 3, 2)
    const dim3 gQkv(HWP / 256, 3 * CC / 64, NB);      // (128, 9, 2)

    // gate = silu(W_gate @ x)
    gemm_bf16_kernel<<<gSmall, 256>>>(w_gate, xhi, xlo, gate, nullptr,
                                      nullptr, nullptr, CC, 1);
    // t = W_qkv @ x
    gemm_bf16_kernel<<<gQkv, 256>>>(w_qkv, xhi, xlo, t, nullptr,
                                    nullptr, nullptr, 3 * CC, 0);
    // qkv = depthwise3x3(t)
    dw_kernel<<<dim3(HH, NB * 3 * CC), 256>>>(t, w_depth, qkv);
    // attention -> split bf16 output
    attn_kernel<<<dim3(HH, 6, NB), 256>>>(qkv, rpb, ahi, alo);
    // y = (W_pre @ attn) * gate   -> split bf16 output
    gemm_bf16_kernel<<<gSmall, 256>>>(w_pre, ahi, alo, nullptr, gate,
                                      yhi, ylo, CC, 2);
    // out = W_out @ y
    gemm_bf16_kernel<<<gSmall, 256>>>(w_out, yhi, ylo, out, nullptr,
                                      nullptr, nullptr, CC, 0);
}

// round 3
// speedup vs baseline: 1.2962x; 1.1265x over previous
#include <cuda_runtime.h>
#include <cuda_bf16.h>
#include <math.h>
#include <stdint.h>

#define HH 128
#define WW 256
#define CC 192
#define HWP (128*256)
#define NB 2

// ---------------- scratch (device globals) ----------------------------------
__device__ float g_gate[NB * CC * HWP];
__device__ float g_t[NB * 3 * CC * HWP];
__device__ float g_qkv[NB * 3 * CC * HWP];
__device__ __nv_bfloat16 g_xhi[NB * CC * HWP];
__device__ __nv_bfloat16 g_xlo[NB * CC * HWP];
__device__ __nv_bfloat16 g_ahi[NB * CC * HWP];
__device__ __nv_bfloat16 g_alo[NB * CC * HWP];
__device__ __nv_bfloat16 g_yhi[NB * CC * HWP];
__device__ __nv_bfloat16 g_ylo[NB * CC * HWP];
// packed weight splits: [qkv(3C) | pre(C) | out(C) | gate(C)] x CC
__device__ __nv_bfloat16 g_whi[6 * CC * CC];
__device__ __nv_bfloat16 g_wlo[6 * CC * CC];

// ---------------- fp32 -> (hi,lo) bf16 split, 4/thread ----------------------
__global__ void __launch_bounds__(256) split4_kernel(
    const float* __restrict__ x, __nv_bfloat16* __restrict__ hi,
    __nv_bfloat16* __restrict__ lo, int n4)
{
    int i = blockIdx.x * 256 + threadIdx.x;
    if (i < n4) {
        float4 v = ((const float4*)x)[i];
        float vs[4] = {v.x, v.y, v.z, v.w};
        __nv_bfloat16 h[4], l[4];
#pragma unroll
        for (int j = 0; j < 4; j++) {
            h[j] = __float2bfloat16(vs[j]);
            l[j] = __float2bfloat16(vs[j] - __bfloat162float(h[j]));
        }
        ((uint2*)hi)[i] = *(uint2*)h;
        ((uint2*)lo)[i] = *(uint2*)l;
    }
}

// ---------------- mma / ldmatrix helpers ------------------------------------
__device__ __forceinline__ void mma16816(float* c, const uint32_t* a,
                                         uint32_t b0, uint32_t b1)
{
    asm volatile(
        "mma.sync.aligned.m16n8k16.row.col.f32.bf16.bf16.f32 "
        "{%0,%1,%2,%3}, {%4,%5,%6,%7}, {%8,%9}, {%0,%1,%2,%3};\n"
        : "+f"(c[0]), "+f"(c[1]), "+f"(c[2]), "+f"(c[3])
        : "r"(a[0]), "r"(a[1]), "r"(a[2]), "r"(a[3]), "r"(b0), "r"(b1));
}

__device__ __forceinline__ void ldsm_x2_t(uint32_t& d0, uint32_t& d1, uint32_t addr)
{
    asm volatile("ldmatrix.sync.aligned.m8n8.x2.trans.shared.b16 {%0,%1}, [%2];\n"
                 : "=r"(d0), "=r"(d1) : "r"(addr));
}

// ---------------- split-bf16 tensor-core GEMM --------------------------------
// Y[b,m,p] = sum_c W[m,c]*X[b,c,p];  W,X given as bf16 hi/lo.
// tile 64(m) x 256(n), BK=16, 8 warps (2x4), double-buffered smem for B.
// epi: 0 f32 out; 1 silu->f32; 2 (*G)->bf16 hi/lo.
#define BROW 264   // B smem row stride in bf16 (528B: conflict-free ldmatrix)

__global__ void __launch_bounds__(256, 2) gemm_bf16_kernel(
    const __nv_bfloat16* __restrict__ Whi, const __nv_bfloat16* __restrict__ Wlo,
    const __nv_bfloat16* __restrict__ Xhi, const __nv_bfloat16* __restrict__ Xlo,
    float* __restrict__ Yf, const float* __restrict__ G,
    __nv_bfloat16* __restrict__ Yhi, __nv_bfloat16* __restrict__ Ylo,
    int M, int epi)
{
    __shared__ __align__(16) __nv_bfloat16 Bs[2][2][16][BROW]; // [buf][half][k][n]

    const int b  = blockIdx.z;
    const int m0 = blockIdx.y * 64;
    const int n0 = blockIdx.x * 256;
    const size_t xoff = (size_t)b * CC * HWP;

    const int tid  = threadIdx.x;
    const int lane = tid & 31;
    const int warp = tid >> 5;
    const int wm   = (warp >> 2) * 32;
    const int wn   = (warp & 3) * 64;
    const int gq   = lane >> 2;
    const int tg   = lane & 3;
    const int bn2  = 2 * lane;

    const uint32_t bs_base = (uint32_t)__cvta_generic_to_shared(&Bs[0][0][0][0]);
    const int krow = lane & 15;       // ldmatrix row (k) for this lane
    // per-(buf,half) ldmatrix row base at n=wn
    const uint32_t lrow = krow * (BROW * 2) + wn * 2;

    float acc[2][8][4];
#pragma unroll
    for (int mt = 0; mt < 2; mt++)
#pragma unroll
        for (int nt = 0; nt < 8; nt++)
#pragma unroll
            for (int i = 0; i < 4; i++) acc[mt][nt][i] = 0.f;

    uint32_t bh[2][4], bl[2][4];
    // prefetch k0=0
#pragma unroll
    for (int r = 0; r < 2; r++) {
        const int k = warp + 8 * r;
#pragma unroll
        for (int j = 0; j < 4; j++) {
            const size_t off = xoff + (size_t)k * HWP + n0 + bn2 + 64 * j;
            bh[r][j] = *(const uint32_t*)(Xhi + off);
            bl[r][j] = *(const uint32_t*)(Xlo + off);
        }
    }
#pragma unroll
    for (int r = 0; r < 2; r++) {
        const int k = warp + 8 * r;
#pragma unroll
        for (int j = 0; j < 4; j++) {
            *(uint32_t*)&Bs[0][0][k][bn2 + 64 * j] = bh[r][j];
            *(uint32_t*)&Bs[0][1][k][bn2 + 64 * j] = bl[r][j];
        }
    }
    __syncthreads();

    const int NK = CC / 16;
    for (int i = 0; i < NK; i++) {
        const int buf = i & 1;
        const int k0  = i * 16;
        // prefetch next tile into regs
        if (i + 1 < NK) {
#pragma unroll
            for (int r = 0; r < 2; r++) {
                const int k = k0 + 16 + warp + 8 * r;
#pragma unroll
                for (int j = 0; j < 4; j++) {
                    const size_t off = xoff + (size_t)k * HWP + n0 + bn2 + 64 * j;
                    bh[r][j] = *(const uint32_t*)(Xhi + off);
                    bl[r][j] = *(const uint32_t*)(Xlo + off);
                }
            }
        }
        // A fragments straight from global (L1-hot; W is tiny)
        uint32_t af[2][2][4];
#pragma unroll
        for (int mt = 0; mt < 2; mt++) {
            const size_t r0 = (size_t)(m0 + wm + mt * 16 + gq) * CC + k0 + 2 * tg;
            const size_t r1 = r0 + 8 * CC;
            af[0][mt][0] = *(const uint32_t*)(Whi + r0);
            af[0][mt][1] = *(const uint32_t*)(Whi + r1);
            af[0][mt][2] = *(const uint32_t*)(Whi + r0 + 8);
            af[0][mt][3] = *(const uint32_t*)(Whi + r1 + 8);
            af[1][mt][0] = *(const uint32_t*)(Wlo + r0);
            af[1][mt][1] = *(const uint32_t*)(Wlo + r1);
            af[1][mt][2] = *(const uint32_t*)(Wlo + r0 + 8);
            af[1][mt][3] = *(const uint32_t*)(Wlo + r1 + 8);
        }
        const uint32_t hb0 = bs_base + (uint32_t)(buf * 2 + 0) * (16 * BROW * 2) + lrow;
        const uint32_t hb1 = bs_base + (uint32_t)(buf * 2 + 1) * (16 * BROW * 2) + lrow;
#pragma unroll
        for (int nt = 0; nt < 8; nt++) {
            uint32_t bh0, bh1, bl0, bl1;
            ldsm_x2_t(bh0, bh1, hb0 + nt * 16);
            ldsm_x2_t(bl0, bl1, hb1 + nt * 16);
#pragma unroll
            for (int mt = 0; mt < 2; mt++) {
                mma16816(acc[mt][nt], af[0][mt], bh0, bh1);  // hi*hi
                mma16816(acc[mt][nt], af[0][mt], bl0, bl1);  // hi*lo
                mma16816(acc[mt][nt], af[1][mt], bh0, bh1);  // lo*hi
            }
        }
        if (i + 1 < NK) {
            const int nb = buf ^ 1;
#pragma unroll
            for (int r = 0; r < 2; r++) {
                const int k = warp + 8 * r;
#pragma unroll
                for (int j = 0; j < 4; j++) {
                    *(uint32_t*)&Bs[nb][0][k][bn2 + 64 * j] = bh[r][j];
                    *(uint32_t*)&Bs[nb][1][k][bn2 + 64 * j] = bl[r][j];
                }
            }
        }
        __syncthreads();
    }

    // epilogue
    const size_t yoff = (size_t)b * M * HWP;
    const size_t goff = (size_t)b * CC * HWP;
#pragma unroll
    for (int mt = 0; mt < 2; mt++) {
        const int r0 = m0 + wm + mt * 16 + gq;
        const int r1 = r0 + 8;
#pragma unroll
        for (int nt = 0; nt < 8; nt++) {
            const int c = n0 + wn + nt * 8 + 2 * tg;
            float v00 = acc[mt][nt][0], v01 = acc[mt][nt][1];
            float v10 = acc[mt][nt][2], v11 = acc[mt][nt][3];
            if (epi == 1) {
                v00 = v00 / (1.f + __expf(-v00));
                v01 = v01 / (1.f + __expf(-v01));
                v10 = v10 / (1.f + __expf(-v10));
                v11 = v11 / (1.f + __expf(-v11));
            }
            if (epi == 2) {
                float2 g0 = *(const float2*)(G + goff + (size_t)r0 * HWP + c);
                float2 g1 = *(const float2*)(G + goff + (size_t)r1 * HWP + c);
                v00 *= g0.x; v01 *= g0.y; v10 *= g1.x; v11 *= g1.y;
                __nv_bfloat16 h00 = __float2bfloat16(v00);
                __nv_bfloat16 h01 = __float2bfloat16(v01);
                __nv_bfloat16 h10 = __float2bfloat16(v10);
                __nv_bfloat16 h11 = __float2bfloat16(v11);
                __nv_bfloat162 hh0; hh0.x = h00; hh0.y = h01;
                __nv_bfloat162 hh1; hh1.x = h10; hh1.y = h11;
                __nv_bfloat162 ll0;
                ll0.x = __float2bfloat16(v00 - __bfloat162float(h00));
                ll0.y = __float2bfloat16(v01 - __bfloat162float(h01));
                __nv_bfloat162 ll1;
                ll1.x = __float2bfloat16(v10 - __bfloat162float(h10));
                ll1.y = __float2bfloat16(v11 - __bfloat162float(h11));
                *(__nv_bfloat162*)(Yhi + yoff + (size_t)r0 * HWP + c) = hh0;
                *(__nv_bfloat162*)(Yhi + yoff + (size_t)r1 * HWP + c) = hh1;
                *(__nv_bfloat162*)(Ylo + yoff + (size_t)r0 * HWP + c) = ll0;
                *(__nv_bfloat162*)(Ylo + yoff + (size_t)r1 * HWP + c) = ll1;
            } else {
                *(float2*)(Yf + yoff + (size_t)r0 * HWP + c) = make_float2(v00, v01);
                *(float2*)(Yf + yoff + (size_t)r1 * HWP + c) = make_float2(v10, v11);
            }
        }
    }
}

// ---------------- depthwise 3x3, 4 px/thread --------------------------------
__global__ void __launch_bounds__(256) dw_kernel(
    const float* __restrict__ t, const float* __restrict__ wd, float* __restrict__ out)
{
    const int cb = blockIdx.y;
    const int c  = cb % (3 * CC);
    const int p  = (blockIdx.x * 256 + threadIdx.x) * 4;
    const int y  = p >> 8;
    const int x  = p & 255;
    const float* base = t + (size_t)cb * HWP;

    float w[9];
#pragma unroll
    for (int i = 0; i < 9; i++) w[i] = wd[c * 9 + i];

    float a0 = 0.f, a1 = 0.f, a2 = 0.f, a3 = 0.f;
#pragma unroll
    for (int dy = -1; dy <= 1; dy++) {
        const int yy = y + dy;
        if (yy < 0 || yy >= HH) continue;
        const float* r = base + yy * WW + x;
        const float4 f = *(const float4*)r;
        const float left  = (x > 0)   ? r[-1] : 0.f;
        const float right = (x < 252) ? r[4]  : 0.f;
        const float w0 = w[(dy + 1) * 3 + 0];
        const float w1 = w[(dy + 1) * 3 + 1];
        const float w2 = w[(dy + 1) * 3 + 2];
        a0 = fmaf(w0, left, fmaf(w1, f.x, fmaf(w2, f.y, a0)));
        a1 = fmaf(w0, f.x,  fmaf(w1, f.y, fmaf(w2, f.z, a1)));
        a2 = fmaf(w0, f.y,  fmaf(w1, f.z, fmaf(w2, f.w, a2)));
        a3 = fmaf(w0, f.z,  fmaf(w1, f.w, fmaf(w2, right, a3)));
    }
    *(float4*)(out + (size_t)cb * HWP + p) = make_float4(a0, a1, a2, a3);
}

// ---------------- row attention (JC=16) --------------------------------------
#define JC 16

__global__ void __launch_bounds__(256, 2) attn_kernel(
    const float* __restrict__ qkv, const float* __restrict__ rpb,
    __nv_bfloat16* __restrict__ ohi, __nv_bfloat16* __restrict__ olo)
{
    __shared__ float Kc[JC][36];
    __shared__ float Vc[JC][36];
    __shared__ float bsh[512];

    const int row = blockIdx.x, head = blockIdx.y, b = blockIdx.z;
    const int tid = threadIdx.x;
    const size_t base = (((size_t)b * (3 * CC) + head * 32) * HH + row) * WW;
    const size_t koff = (size_t)CC * HWP;
    const size_t voff = 2 * koff;

    for (int i = tid; i < 511; i += 256) bsh[i] = rpb[i * 6 + head];

    float q[32];
#pragma unroll
    for (int d = 0; d < 32; d++) q[d] = qkv[base + (size_t)d * HWP + tid];

    const float scale = 0.17677669529663687f;
    float m = -1e30f, l = 0.f;
    float o[32];
#pragma unroll
    for (int d = 0; d < 32; d++) o[d] = 0.f;

    for (int jt = 0; jt < WW; jt += JC) {
        __syncthreads();
        for (int i = tid; i < JC * 32; i += 256) {
            const int j = i & (JC - 1);
            const int d = i >> 4;
            Kc[j][d] = qkv[base + koff + (size_t)d * HWP + jt + j];
            Vc[j][d] = qkv[base + voff + (size_t)d * HWP + jt + j];
        }
        __syncthreads();

        float s[JC];
#pragma unroll
        for (int jj = 0; jj < JC; jj++) {
            const float4* kp = (const float4*)&Kc[jj][0];
            float acc = 0.f;
#pragma unroll
            for (int c4 = 0; c4 < 8; c4++) {
                float4 kv = kp[c4];
                acc = fmaf(q[c4 * 4 + 0], kv.x, acc);
                acc = fmaf(q[c4 * 4 + 1], kv.y, acc);
                acc = fmaf(q[c4 * 4 + 2], kv.z, acc);
                acc = fmaf(q[c4 * 4 + 3], kv.w, acc);
            }
            s[jj] = acc * scale + bsh[tid - (jt + jj) + 255];
        }
        float mc = m;
#pragma unroll
        for (int jj = 0; jj < JC; jj++) mc = fmaxf(mc, s[jj]);
        const float corr = __expf(m - mc);
        l *= corr;
#pragma unroll
        for (int d = 0; d < 32; d++) o[d] *= corr;
#pragma unroll
        for (int jj = 0; jj < JC; jj++) {
            const float p = __expf(s[jj] - mc);
            l += p;
            const float4* vp = (const float4*)&Vc[jj][0];
#pragma unroll
            for (int c4 = 0; c4 < 8; c4++) {
                float4 vv = vp[c4];
                o[c4 * 4 + 0] = fmaf(p, vv.x, o[c4 * 4 + 0]);
                o[c4 * 4 + 1] = fmaf(p, vv.y, o[c4 * 4 + 1]);
                o[c4 * 4 + 2] = fmaf(p, vv.z, o[c4 * 4 + 2]);
                o[c4 * 4 + 3] = fmaf(p, vv.w, o[c4 * 4 + 3]);
            }
        }
        m = mc;
    }

    const float inv = 1.f / l;
    const size_t obase = (((size_t)b * CC + head * 32) * HH + row) * WW;
#pragma unroll
    for (int d = 0; d < 32; d++) {
        const float v = o[d] * inv;
        __nv_bfloat16 h = __float2bfloat16(v);
        ohi[obase + (size_t)d * HWP + tid] = h;
        olo[obase + (size_t)d * HWP + tid] = __float2bfloat16(v - __bfloat162float(h));
    }
}

// ---------------- launch ------------------------------------------------------
extern "C" void kernel_launch(void* const* d_in, const int* in_sizes, int n_in,
                              void* d_out, int out_size)
{
    const float* x       = (const float*)d_in[0];
    const float* rpb     = (const float*)d_in[1];
    const float* w_qkv   = (const float*)d_in[2];
    const float* w_depth = (const float*)d_in[3];
    const float* w_pre   = (const float*)d_in[4];
    const float* w_out   = (const float*)d_in[5];
    const float* w_gate  = (const float*)d_in[6];
    float* out = (float*)d_out;
    (void)in_sizes; (void)n_in; (void)out_size;

    float *gate, *t, *qkv;
    __nv_bfloat16 *xhi, *xlo, *ahi, *alo, *yhi, *ylo, *whi, *wlo;
    cudaGetSymbolAddress((void**)&gate, g_gate);
    cudaGetSymbolAddress((void**)&t,    g_t);
    cudaGetSymbolAddress((void**)&qkv,  g_qkv);
    cudaGetSymbolAddress((void**)&xhi,  g_xhi);
    cudaGetSymbolAddress((void**)&xlo,  g_xlo);
    cudaGetSymbolAddress((void**)&ahi,  g_ahi);
    cudaGetSymbolAddress((void**)&alo,  g_alo);
    cudaGetSymbolAddress((void**)&yhi,  g_yhi);
    cudaGetSymbolAddress((void**)&ylo,  g_ylo);
    cudaGetSymbolAddress((void**)&whi,  g_whi);
    cudaGetSymbolAddress((void**)&wlo,  g_wlo);

    // weight splits into packed buffer
    const int WQ = 3 * CC * CC;            // qkv weights
    const int WS = CC * CC;                // each small weight
    split4_kernel<<<(WQ / 4 + 255) / 256, 256>>>(w_qkv,  whi,               wlo,               WQ / 4);
    split4_kernel<<<(WS / 4 + 255) / 256, 256>>>(w_pre,  whi + 3 * WS,      wlo + 3 * WS,      WS / 4);
    split4_kernel<<<(WS / 4 + 255) / 256, 256>>>(w_out,  whi + 4 * WS,      wlo + 4 * WS,      WS / 4);
    split4_kernel<<<(WS / 4 + 255) / 256, 256>>>(w_gate, whi + 5 * WS,      wlo + 5 * WS,      WS / 4);

    const int nx = NB * CC * HWP;
    split4_kernel<<<(nx / 4 + 255) / 256, 256>>>(x, xhi, xlo, nx / 4);

    const dim3 gSmall(HWP / 256, CC / 64, NB);        // (128, 3, 2)
    const dim3 gQkv(HWP / 256, 3 * CC / 64, NB);      // (128, 9, 2)

    // gate = silu(W_gate @ x)
    gemm_bf16_kernel<<<gSmall, 256>>>(whi + 5 * WS, wlo + 5 * WS, xhi, xlo,
                                      gate, nullptr, nullptr, nullptr, CC, 1);
    // t = W_qkv @ x
    gemm_bf16_kernel<<<gQkv, 256>>>(whi, wlo, xhi, xlo,
                                    t, nullptr, nullptr, nullptr, 3 * CC, 0);
    // qkv = depthwise3x3(t)
    dw_kernel<<<dim3(HWP / 1024, NB * 3 * CC), 256>>>(t, w_depth, qkv);
    // attention -> split bf16 output
    attn_kernel<<<dim3(HH, 6, NB), 256>>>(qkv, rpb, ahi, alo);
    // y = (W_pre @ attn) * gate -> split bf16
    gemm_bf16_kernel<<<gSmall, 256>>>(whi + 3 * WS, wlo + 3 * WS, ahi, alo,
                                      nullptr, gate, yhi, ylo, CC, 2);
    // out = W_out @ y
    gemm_bf16_kernel<<<gSmall, 256>>>(whi + 4 * WS, wlo + 4 * WS, yhi, ylo,
                                      out, nullptr, nullptr, nullptr, CC, 0);
}